// round 3
// baseline (speedup 1.0000x reference)
#include <cuda_runtime.h>
#include <math.h>

#define CONTF 13
#define CATEF 26
#define NF    39      // CONTF + CATEF
#define ED    40      // embedding dim
#define NPAIR 741     // 39*38/2
#define NA    8       // attention dim
#define TPB   256
#define PAD   41      // xs row stride (gcd(41,32)=1 -> conflict-free)
#define VOCAB 100000

__device__ int g_is64;

// Detect whether cates is int64 or int32. If int64 (values < VOCAB, >=0),
// the high 32-bit word of every element is 0. If int32, the "high word"
// position holds another random index in [0,100000) -> virtually never all 0.
__global__ void detect_dtype_kernel(const unsigned int* __restrict__ raw) {
    if (threadIdx.x == 0) {
        int is64 = 1;
        #pragma unroll 1
        for (int k = 0; k < 128; k++) {
            unsigned int lo = raw[2 * k];
            unsigned int hi = raw[2 * k + 1];
            if (hi != 0u || lo >= (unsigned)VOCAB) { is64 = 0; break; }
        }
        g_is64 = is64;
    }
}

// Decode linear pair index p -> (i, j), i<j, row-major triu(k=1) of 39 fields.
// start(i) = i*(77-i)/2
__device__ __forceinline__ void decode_pair(int p, int& i, int& j) {
    float s = sqrtf((float)(5929 - 8 * p));
    int ii = (int)floorf((77.0f - s) * 0.5f);
    while (ii > 0 && ii * (77 - ii) / 2 > p) ii--;
    while ((ii + 1) * (76 - ii) / 2 <= p) ii++;
    i = ii;
    j = p - ii * (77 - ii) / 2 + ii + 1;
}

__global__ __launch_bounds__(TPB) void afm_main(
    const float* __restrict__ conts,
    const void*  __restrict__ cates_raw,
    const float* __restrict__ emb,
    const float* __restrict__ attn_W,   // (8, 40) row-major
    const float* __restrict__ attn_b,   // (8,)
    const float* __restrict__ proj_W,   // (1, 8)
    const float* __restrict__ fc_W,     // (1, 40)
    const float* __restrict__ fc_b,     // (1,)
    float* __restrict__ out)            // (B, 1)
{
    // 16B alignment is REQUIRED: Ws is read with LDS.128 (float4 casts).
    __shared__ __align__(16) float Ws[ED * NA]; // attn_W transposed: [d][a]
    __shared__ float xs[NF * PAD];      // x tile, padded rows
    __shared__ float pwb[2 * NA];       // [0:8) attn_b, [8:16) proj_W
    __shared__ float fcw[ED];
    __shared__ float sredm[8], sreds[8];
    __shared__ float red[8 * ED];
    __shared__ float red2[ED];

    const int b    = blockIdx.x;
    const int t    = threadIdx.x;
    const int lane = t & 31;
    const int wid  = t >> 5;

    // --- Load parameters into smem ---
    for (int e = t; e < ED * NA; e += TPB) {
        int a = e / ED, d = e - a * ED;       // attn_W[a*ED + d]
        Ws[d * NA + a] = attn_W[e];
    }
    if (t < NA) { pwb[t] = attn_b[t]; pwb[NA + t] = proj_W[t]; }
    if (t < ED) fcw[t] = fc_W[t];

    // --- Build x tile: 13 cont rows (scaled emb rows 0..12) + 26 gathered rows ---
    const int is64 = g_is64;
    const long long* c64 = (const long long*)cates_raw;
    const int*       c32 = (const int*)cates_raw;

    for (int e = t; e < NF * ED; e += TPB) {
        int r = e / ED, d = e - r * ED;
        float v;
        if (r < CONTF) {
            v = emb[r * ED + d] * conts[b * CONTF + r];
        } else {
            int f = r - CONTF;
            long long idx = is64 ? c64[(long long)b * CATEF + f]
                                 : (long long)c32[b * CATEF + f];
            v = emb[idx * ED + d];
        }
        xs[r * PAD + d] = v;
    }
    __syncthreads();

    // --- Each thread owns up to 3 pairs: t, t+256, t+512 ---
    const int p0 = t, p1 = t + TPB, p2 = t + 2 * TPB;
    const bool v2 = (p2 < NPAIR);            // p0,p1 always valid (741 > 512)
    int i0, j0, i1, j1, i2, j2;
    decode_pair(p0, i0, j0);
    decode_pair(p1, i1, j1);
    if (v2) decode_pair(p2, i2, j2); else { i2 = 0; j2 = 1; }

    const float* xr0 = xs + i0 * PAD; const float* xc0 = xs + j0 * PAD;
    const float* xr1 = xs + i1 * PAD; const float* xc1 = xs + j1 * PAD;
    const float* xr2 = xs + i2 * PAD; const float* xc2 = xs + j2 * PAD;

    // --- Pass 1: logits for 3 pairs (attn GEMV fused) ---
    float acc0[NA], acc1[NA], acc2[NA];
    #pragma unroll
    for (int a = 0; a < NA; a++) {
        float bv = pwb[a];
        acc0[a] = bv; acc1[a] = bv; acc2[a] = bv;
    }

    #pragma unroll 8
    for (int d = 0; d < ED; d++) {
        float4 wlo = *(const float4*)&Ws[d * NA];
        float4 whi = *(const float4*)&Ws[d * NA + 4];
        float e0 = xr0[d] * xc0[d];
        float e1 = xr1[d] * xc1[d];
        float e2 = xr2[d] * xc2[d];
        acc0[0] += e0 * wlo.x; acc0[1] += e0 * wlo.y; acc0[2] += e0 * wlo.z; acc0[3] += e0 * wlo.w;
        acc0[4] += e0 * whi.x; acc0[5] += e0 * whi.y; acc0[6] += e0 * whi.z; acc0[7] += e0 * whi.w;
        acc1[0] += e1 * wlo.x; acc1[1] += e1 * wlo.y; acc1[2] += e1 * wlo.z; acc1[3] += e1 * wlo.w;
        acc1[4] += e1 * whi.x; acc1[5] += e1 * whi.y; acc1[6] += e1 * whi.z; acc1[7] += e1 * whi.w;
        acc2[0] += e2 * wlo.x; acc2[1] += e2 * wlo.y; acc2[2] += e2 * wlo.z; acc2[3] += e2 * wlo.w;
        acc2[4] += e2 * whi.x; acc2[5] += e2 * whi.y; acc2[6] += e2 * whi.z; acc2[7] += e2 * whi.w;
    }

    float g0 = 0.f, g1 = 0.f, g2 = 0.f;
    #pragma unroll
    for (int a = 0; a < NA; a++) {
        float p = pwb[NA + a];
        g0 += p * fmaxf(acc0[a], 0.f);
        g1 += p * fmaxf(acc1[a], 0.f);
        g2 += p * fmaxf(acc2[a], 0.f);
    }

    // --- Softmax: block max ---
    float m = fmaxf(g0, g1);
    if (v2) m = fmaxf(m, g2);
    #pragma unroll
    for (int o = 16; o; o >>= 1) m = fmaxf(m, __shfl_xor_sync(0xffffffffu, m, o));
    if (lane == 0) sredm[wid] = m;
    __syncthreads();
    float gmax = sredm[0];
    #pragma unroll
    for (int k = 1; k < 8; k++) gmax = fmaxf(gmax, sredm[k]);

    float w0 = __expf(g0 - gmax);
    float w1 = __expf(g1 - gmax);
    float w2 = v2 ? __expf(g2 - gmax) : 0.f;

    // --- Softmax: block sum ---
    float s = w0 + w1 + w2;
    #pragma unroll
    for (int o = 16; o; o >>= 1) s += __shfl_xor_sync(0xffffffffu, s, o);
    if (lane == 0) sreds[wid] = s;
    __syncthreads();
    float gsum = 0.f;
    #pragma unroll
    for (int k = 0; k < 8; k++) gsum += sreds[k];

    // --- Pass 2: weighted pool (recompute ewp, accumulate 40 dims in regs) ---
    float pa[ED];
    #pragma unroll 8
    for (int d = 0; d < ED; d++) {
        float v = w0 * (xr0[d] * xc0[d]);
        v += w1 * (xr1[d] * xc1[d]);
        v += w2 * (xr2[d] * xc2[d]);
        pa[d] = v;
    }
    #pragma unroll
    for (int d = 0; d < ED; d++) {
        #pragma unroll
        for (int o = 16; o; o >>= 1) pa[d] += __shfl_xor_sync(0xffffffffu, pa[d], o);
    }
    if (lane == 0) {
        #pragma unroll
        for (int d = 0; d < ED; d++) red[wid * ED + d] = pa[d];
    }
    __syncthreads();

    if (t < ED) {
        float sd = 0.f;
        #pragma unroll
        for (int w = 0; w < 8; w++) sd += red[w * ED + t];
        red2[t] = (sd / gsum) * fcw[t];
    }
    __syncthreads();

    if (t == 0) {
        float z = fc_b[0];
        #pragma unroll
        for (int d = 0; d < ED; d++) z += red2[d];
        out[b] = 1.f / (1.f + __expf(-z));
    }
}

extern "C" void kernel_launch(void* const* d_in, const int* in_sizes, int n_in,
                              void* d_out, int out_size) {
    // metadata order: conts, cates, combs(unused), emb_table, attn_W, attn_b,
    //                 proj_W, fc_W, fc_b
    const float* conts  = (const float*)d_in[0];
    const void*  cates  = d_in[1];
    const float* emb    = (const float*)d_in[3];
    const float* attn_W = (const float*)d_in[4];
    const float* attn_b = (const float*)d_in[5];
    const float* proj_W = (const float*)d_in[6];
    const float* fc_W   = (const float*)d_in[7];
    const float* fc_b   = (const float*)d_in[8];
    float* out = (float*)d_out;

    int batch = in_sizes[0] / CONTF;

    detect_dtype_kernel<<<1, 32>>>((const unsigned int*)cates);
    afm_main<<<batch, TPB>>>(conts, cates, emb, attn_W, attn_b, proj_W,
                             fc_W, fc_b, out);
}

// round 5
// speedup vs baseline: 1.4729x; 1.4729x over previous
#include <cuda_runtime.h>
#include <math.h>

#define CONTF 13
#define CATEF 26
#define NF    39
#define ED    40
#define NPAIR 741
#define NA    8
#define TPB   384
#define NW    (TPB/32)
#define PAD   44      // 176B row stride: 16B-aligned, conflict-free for LDS.128
#define VOCAB 100000

typedef unsigned long long u64;

__device__ __forceinline__ u64 mul2(u64 a, u64 b) {
    u64 d; asm("mul.rn.f32x2 %0, %1, %2;" : "=l"(d) : "l"(a), "l"(b)); return d;
}
__device__ __forceinline__ u64 fma2(u64 a, u64 b, u64 c) {
    u64 d; asm("fma.rn.f32x2 %0, %1, %2, %3;" : "=l"(d) : "l"(a), "l"(b), "l"(c)); return d;
}
__device__ __forceinline__ u64 pk2(float lo, float hi) {
    u64 d; asm("mov.b64 %0, {%1, %2};" : "=l"(d) : "f"(lo), "f"(hi)); return d;
}
__device__ __forceinline__ float sum2(u64 v) {   // lo + hi
    float lo, hi; asm("mov.b64 {%0, %1}, %2;" : "=f"(lo), "=f"(hi) : "l"(v));
    return lo + hi;
}

// Decode linear pair index p -> (i, j), i<j, row-major triu(k=1) of 39 fields.
__device__ __forceinline__ void decode_pair(int p, int& i, int& j) {
    float s = sqrtf((float)(5929 - 8 * p));
    int ii = (int)floorf((77.0f - s) * 0.5f);
    while (ii > 0 && ii * (77 - ii) / 2 > p) ii--;
    while ((ii + 1) * (76 - ii) / 2 <= p) ii++;
    i = ii;
    j = p - ii * (77 - ii) / 2 + ii + 1;
}

__global__ __launch_bounds__(TPB, 2) void afm_main(
    const float* __restrict__ conts,
    const void*  __restrict__ cates_raw,
    const float* __restrict__ emb,
    const float* __restrict__ attn_W,   // (8, 40) row-major
    const float* __restrict__ attn_b,   // (8,)
    const float* __restrict__ proj_W,   // (1, 8)
    const float* __restrict__ fc_W,     // (1, 40)
    const float* __restrict__ fc_b,     // (1,)
    float* __restrict__ out)            // (B, 1)
{
    __shared__ __align__(16) float xs[NF * PAD];
    __shared__ __align__(16) u64 Wp[20 * NA];   // [dp][a] = (W[2dp][a], W[2dp+1][a])
    __shared__ __align__(16) u64 fp[20];        // (fc[2dp], fc[2dp+1])
    __shared__ float pwb[2 * NA];               // attn_b | proj_W
    __shared__ float sredm[NW], sreds[NW], sredq[NW];
    __shared__ int   sflag;

    const int b    = blockIdx.x;
    const int t    = threadIdx.x;
    const int lane = t & 31;
    const int wid  = t >> 5;

    // --- int64-vs-int32 probe (warp 0): int64 indices < VOCAB -> hi words 0 ---
    if (wid == 0) {
        const unsigned int* raw = (const unsigned int*)cates_raw;
        unsigned int lo = raw[2 * lane], hi = raw[2 * lane + 1];
        int ok = (hi == 0u && lo < (unsigned)VOCAB);
        unsigned int bal = __ballot_sync(0xffffffffu, ok);
        if (lane == 0) sflag = (bal == 0xffffffffu);
    }

    // --- pack parameters into smem ---
    for (int e = t; e < 20 * NA; e += TPB) {
        int dp = e >> 3, a = e & 7;
        Wp[e] = pk2(attn_W[a * ED + 2 * dp], attn_W[a * ED + 2 * dp + 1]);
    }
    if (t < 20) fp[t] = pk2(fc_W[2 * t], fc_W[2 * t + 1]);
    if (t < NA) { pwb[t] = attn_b[t]; pwb[NA + t] = proj_W[t]; }
    __syncthreads();

    // --- build x tile ---
    const int is64 = sflag;
    const long long* c64 = (const long long*)cates_raw;
    const int*       c32 = (const int*)cates_raw;
    for (int e = t; e < NF * ED; e += TPB) {
        int r = e / ED, d = e - r * ED;
        float v;
        if (r < CONTF) {
            v = emb[r * ED + d] * conts[b * CONTF + r];
        } else {
            int f = r - CONTF;
            long long idx = is64 ? c64[(long long)b * CATEF + f]
                                 : (long long)c32[b * CATEF + f];
            v = emb[idx * ED + d];
        }
        xs[r * PAD + d] = v;
    }
    __syncthreads();

    // --- 2 pairs per thread: p0 = t (<741 always), p1 = t + 384 ---
    const int p0 = t;
    const int p1v = t + TPB;
    const bool v1 = (p1v < NPAIR);
    const int p1 = v1 ? p1v : (NPAIR - 1);
    int i0, j0, i1, j1;
    decode_pair(p0, i0, j0);
    decode_pair(p1, i1, j1);

    const ulonglong2* xr0 = (const ulonglong2*)(xs + i0 * PAD);
    const ulonglong2* xc0 = (const ulonglong2*)(xs + j0 * PAD);
    const ulonglong2* xr1 = (const ulonglong2*)(xs + i1 * PAD);
    const ulonglong2* xc1 = (const ulonglong2*)(xs + j1 * PAD);

    // packed accumulators: (even-d, odd-d) halves per attention unit
    u64 acc0[NA], acc1[NA];
    #pragma unroll
    for (int a = 0; a < NA; a++) { acc0[a] = 0ull; acc1[a] = 0ull; }
    u64 q0 = 0ull, q1 = 0ull;

    #pragma unroll
    for (int dv = 0; dv < 10; dv++) {          // 4 dims per iter (2 packed lanes)
        ulonglong2 r0 = xr0[dv], c0 = xc0[dv];
        ulonglong2 r1 = xr1[dv], c1 = xc1[dv];
        u64 e0a = mul2(r0.x, c0.x), e0b = mul2(r0.y, c0.y);
        u64 e1a = mul2(r1.x, c1.x), e1b = mul2(r1.y, c1.y);
        const ulonglong2* wrow = (const ulonglong2*)(Wp + (dv * 2) * NA);
        #pragma unroll
        for (int k = 0; k < 4; k++) {          // dp0: a = 2k, 2k+1
            ulonglong2 wv = wrow[k];
            acc0[2 * k]     = fma2(e0a, wv.x, acc0[2 * k]);
            acc0[2 * k + 1] = fma2(e0a, wv.y, acc0[2 * k + 1]);
            acc1[2 * k]     = fma2(e1a, wv.x, acc1[2 * k]);
            acc1[2 * k + 1] = fma2(e1a, wv.y, acc1[2 * k + 1]);
        }
        #pragma unroll
        for (int k = 0; k < 4; k++) {          // dp1
            ulonglong2 wv = wrow[4 + k];
            acc0[2 * k]     = fma2(e0b, wv.x, acc0[2 * k]);
            acc0[2 * k + 1] = fma2(e0b, wv.y, acc0[2 * k + 1]);
            acc1[2 * k]     = fma2(e1b, wv.x, acc1[2 * k]);
            acc1[2 * k + 1] = fma2(e1b, wv.y, acc1[2 * k + 1]);
        }
        q0 = fma2(e0a, fp[2 * dv], q0); q0 = fma2(e0b, fp[2 * dv + 1], q0);
        q1 = fma2(e1a, fp[2 * dv], q1); q1 = fma2(e1b, fp[2 * dv + 1], q1);
    }

    // --- logits: relu + proj ---
    float g0 = 0.f, g1 = 0.f;
    #pragma unroll
    for (int a = 0; a < NA; a++) {
        float h0 = sum2(acc0[a]) + pwb[a];
        float h1 = sum2(acc1[a]) + pwb[a];
        g0 += pwb[NA + a] * fmaxf(h0, 0.f);
        g1 += pwb[NA + a] * fmaxf(h1, 0.f);
    }
    float qs0 = sum2(q0), qs1 = sum2(q1);

    // --- block max ---
    float m = v1 ? fmaxf(g0, g1) : g0;
    #pragma unroll
    for (int o = 16; o; o >>= 1) m = fmaxf(m, __shfl_xor_sync(0xffffffffu, m, o));
    if (lane == 0) sredm[wid] = m;
    __syncthreads();
    float gmax = sredm[0];
    #pragma unroll
    for (int k = 1; k < NW; k++) gmax = fmaxf(gmax, sredm[k]);

    float w0 = __expf(g0 - gmax);
    float w1 = v1 ? __expf(g1 - gmax) : 0.f;

    // --- block sums of (w, w*q) ---
    float s  = w0 + w1;
    float sq = w0 * qs0 + w1 * qs1;
    #pragma unroll
    for (int o = 16; o; o >>= 1) {
        s  += __shfl_xor_sync(0xffffffffu, s,  o);
        sq += __shfl_xor_sync(0xffffffffu, sq, o);
    }
    if (lane == 0) { sreds[wid] = s; sredq[wid] = sq; }
    __syncthreads();

    if (t == 0) {
        float ts = 0.f, tq = 0.f;
        #pragma unroll
        for (int k = 0; k < NW; k++) { ts += sreds[k]; tq += sredq[k]; }
        float z = tq / ts + fc_b[0];
        out[b] = 1.f / (1.f + __expf(-z));
    }
}

extern "C" void kernel_launch(void* const* d_in, const int* in_sizes, int n_in,
                              void* d_out, int out_size) {
    const float* conts  = (const float*)d_in[0];
    const void*  cates  = d_in[1];
    const float* emb    = (const float*)d_in[3];
    const float* attn_W = (const float*)d_in[4];
    const float* attn_b = (const float*)d_in[5];
    const float* proj_W = (const float*)d_in[6];
    const float* fc_W   = (const float*)d_in[7];
    const float* fc_b   = (const float*)d_in[8];
    float* out = (float*)d_out;

    int batch = in_sizes[0] / CONTF;
    afm_main<<<batch, TPB>>>(conts, cates, emb, attn_W, attn_b, proj_W,
                             fc_W, fc_b, out);
}

// round 6
// speedup vs baseline: 1.7744x; 1.2047x over previous
#include <cuda_runtime.h>
#include <math.h>
#include <stdint.h>

#define CONTF 13
#define CATEF 26
#define NF    39
#define ED    40
#define NPAIR 741
#define NA    8
#define TPB   384
#define NW    (TPB/32)
#define PAD   44      // 176B row stride: 16B-aligned, conflict-free LDS.128
#define XSZ   (NF*PAD)
#define VOCAB 100000
#define NBLK  296     // 2 persistent blocks per SM (148 SMs)

typedef unsigned long long u64;

__device__ __forceinline__ u64 mul2(u64 a, u64 b) {
    u64 d; asm("mul.rn.f32x2 %0, %1, %2;" : "=l"(d) : "l"(a), "l"(b)); return d;
}
__device__ __forceinline__ u64 fma2(u64 a, u64 b, u64 c) {
    u64 d; asm("fma.rn.f32x2 %0, %1, %2, %3;" : "=l"(d) : "l"(a), "l"(b), "l"(c)); return d;
}
__device__ __forceinline__ u64 pk2(float lo, float hi) {
    u64 d; asm("mov.b64 %0, {%1, %2};" : "=l"(d) : "f"(lo), "f"(hi)); return d;
}
__device__ __forceinline__ float sum2(u64 v) {
    float lo, hi; asm("mov.b64 {%0, %1}, %2;" : "=f"(lo), "=f"(hi) : "l"(v));
    return lo + hi;
}
__device__ __forceinline__ void cp16(uint32_t dst, const void* src) {
    asm volatile("cp.async.ca.shared.global [%0], [%1], 16;" :: "r"(dst), "l"(src));
}
__device__ __forceinline__ void cp4(uint32_t dst, const void* src) {
    asm volatile("cp.async.ca.shared.global [%0], [%1], 4;" :: "r"(dst), "l"(src));
}

// Decode linear pair index p -> (i, j), i<j, row-major triu(k=1) of 39 fields.
__device__ __forceinline__ void decode_pair(int p, int& i, int& j) {
    float s = sqrtf((float)(5929 - 8 * p));
    int ii = (int)floorf((77.0f - s) * 0.5f);
    while (ii > 0 && ii * (77 - ii) / 2 > p) ii--;
    while ((ii + 1) * (76 - ii) / 2 <= p) ii++;
    i = ii;
    j = p - ii * (77 - ii) / 2 + ii + 1;
}

__global__ __launch_bounds__(TPB, 2) void afm_main(
    const float* __restrict__ conts,
    const void*  __restrict__ cates_raw,
    const float* __restrict__ emb,
    const float* __restrict__ attn_W,   // (8, 40)
    const float* __restrict__ attn_b,   // (8,)
    const float* __restrict__ proj_W,   // (1, 8)
    const float* __restrict__ fc_W,     // (1, 40)
    const float* __restrict__ fc_b,     // (1,)
    float* __restrict__ out,            // (B, 1)
    int batch)
{
    __shared__ __align__(16) float xs[2][XSZ];        // double-buffered x tiles
    __shared__ __align__(16) u64 Wp[20 * NA];         // [dp][a]=(W[2dp][a],W[2dp+1][a])
    __shared__ __align__(16) ulonglong2 fp2[10];      // fc_W packed, 4 dims/entry
    __shared__ float sbase[CONTF * ED];               // emb rows 0..12 (block-lifetime)
    __shared__ float sconts[2][CONTF];
    __shared__ float pwb[2 * NA];                     // attn_b | proj_W
    __shared__ float sredm[NW], sreds[NW], sredq[NW];
    __shared__ int   sflag;

    const int t    = threadIdx.x;
    const int lane = t & 31;
    const int wid  = t >> 5;

    // --- int64-vs-int32 probe: int64 indices < VOCAB -> all hi words 0 ---
    if (wid == 0) {
        const unsigned int* raw = (const unsigned int*)cates_raw;
        unsigned int lo = raw[2 * lane], hi = raw[2 * lane + 1];
        int ok = (hi == 0u && lo < (unsigned)VOCAB);
        unsigned int bal = __ballot_sync(0xffffffffu, ok);
        if (lane == 0) sflag = (bal == 0xffffffffu);
    }

    // --- block-lifetime parameter setup ---
    for (int e = t; e < 20 * NA; e += TPB) {
        int dp = e >> 3, a = e & 7;
        Wp[e] = pk2(attn_W[a * ED + 2 * dp], attn_W[a * ED + 2 * dp + 1]);
    }
    if (t < 10) {
        ulonglong2 v;
        v.x = pk2(fc_W[4 * t], fc_W[4 * t + 1]);
        v.y = pk2(fc_W[4 * t + 2], fc_W[4 * t + 3]);
        fp2[t] = v;
    }
    if (t < NA) { pwb[t] = attn_b[t]; pwb[NA + t] = proj_W[t]; }
    for (int e = t; e < CONTF * ED; e += TPB) sbase[e] = emb[e];  // rows 0..12 contiguous
    __syncthreads();

    const int is64 = sflag;
    const long long* c64 = (const long long*)cates_raw;
    const int*       c32 = (const int*)cates_raw;
    const float fcb = fc_b[0];

    const uint32_t xs_a = (uint32_t)__cvta_generic_to_shared(&xs[0][0]);
    const uint32_t sc_a = (uint32_t)__cvta_generic_to_shared(&sconts[0][0]);

    // --- hoisted per-thread pair geometry (constant across samples) ---
    const int p0 = t;
    const int p1v = t + TPB;
    const bool v1 = (p1v < NPAIR);
    const int p1 = v1 ? p1v : (NPAIR - 1);
    int i0, j0, i1, j1;
    decode_pair(p0, i0, j0);
    decode_pair(p1, i1, j1);
    const int or0 = i0 * PAD, oc0 = j0 * PAD, or1 = i1 * PAD, oc1 = j1 * PAD;

    // --- prefetch: 26 gathered rows (260 threads x 16B segs) + 13 conts ---
    #define PREFETCH(b_, buf_) do {                                           \
        if (t < 260) {                                                        \
            int f_ = t / 10, seg_ = t - f_ * 10;                              \
            long long idx_ = is64 ? c64[(long long)(b_) * CATEF + f_]         \
                                  : (long long)c32[(b_) * CATEF + f_];        \
            cp16(xs_a + ((buf_) * XSZ + (CONTF + f_) * PAD + seg_ * 4) * 4,   \
                 emb + idx_ * ED + seg_ * 4);                                 \
        } else if (t < 260 + CONTF) {                                         \
            int r_ = t - 260;                                                 \
            cp4(sc_a + ((buf_) * CONTF + r_) * 4, conts + (b_) * CONTF + r_); \
        }                                                                     \
        asm volatile("cp.async.commit_group;" ::: "memory");                  \
    } while (0)

    const int s0 = blockIdx.x;
    int parity = 0;
    if (s0 < batch) PREFETCH(s0, 0);

    for (int s = s0; s < batch; s += NBLK) {
        float* xb = &xs[parity][0];

        asm volatile("cp.async.wait_group 0;" ::: "memory");
        __syncthreads();

        // overlap next sample's gather with this sample's compute
        if (s + NBLK < batch) PREFETCH(s + NBLK, parity ^ 1);

        // build continuous-field rows: sbase * conts[s]
        for (int e = t; e < CONTF * ED; e += TPB) {
            int r = e / ED, d = e - r * ED;
            xb[r * PAD + d] = sbase[e] * sconts[parity][r];
        }
        __syncthreads();

        const ulonglong2* xr0 = (const ulonglong2*)(xb + or0);
        const ulonglong2* xc0 = (const ulonglong2*)(xb + oc0);
        const ulonglong2* xr1 = (const ulonglong2*)(xb + or1);
        const ulonglong2* xc1 = (const ulonglong2*)(xb + oc1);

        u64 acc0[NA], acc1[NA];
        #pragma unroll
        for (int a = 0; a < NA; a++) { acc0[a] = 0ull; acc1[a] = 0ull; }
        u64 q0 = 0ull, q1 = 0ull;

        #pragma unroll
        for (int dv = 0; dv < 10; dv++) {          // 4 dims per iter
            ulonglong2 r0 = xr0[dv], c0 = xc0[dv];
            ulonglong2 r1 = xr1[dv], c1 = xc1[dv];
            u64 e0a = mul2(r0.x, c0.x), e0b = mul2(r0.y, c0.y);
            u64 e1a = mul2(r1.x, c1.x), e1b = mul2(r1.y, c1.y);
            const ulonglong2* wrow = (const ulonglong2*)(Wp + (dv * 2) * NA);
            #pragma unroll
            for (int k = 0; k < 4; k++) {
                ulonglong2 wv = wrow[k];
                acc0[2 * k]     = fma2(e0a, wv.x, acc0[2 * k]);
                acc0[2 * k + 1] = fma2(e0a, wv.y, acc0[2 * k + 1]);
                acc1[2 * k]     = fma2(e1a, wv.x, acc1[2 * k]);
                acc1[2 * k + 1] = fma2(e1a, wv.y, acc1[2 * k + 1]);
            }
            #pragma unroll
            for (int k = 0; k < 4; k++) {
                ulonglong2 wv = wrow[4 + k];
                acc0[2 * k]     = fma2(e0b, wv.x, acc0[2 * k]);
                acc0[2 * k + 1] = fma2(e0b, wv.y, acc0[2 * k + 1]);
                acc1[2 * k]     = fma2(e1b, wv.x, acc1[2 * k]);
                acc1[2 * k + 1] = fma2(e1b, wv.y, acc1[2 * k + 1]);
            }
            ulonglong2 fv = fp2[dv];
            q0 = fma2(e0a, fv.x, q0); q0 = fma2(e0b, fv.y, q0);
            q1 = fma2(e1a, fv.x, q1); q1 = fma2(e1b, fv.y, q1);
        }

        float g0 = 0.f, g1 = 0.f;
        #pragma unroll
        for (int a = 0; a < NA; a++) {
            float h0 = sum2(acc0[a]) + pwb[a];
            float h1 = sum2(acc1[a]) + pwb[a];
            g0 += pwb[NA + a] * fmaxf(h0, 0.f);
            g1 += pwb[NA + a] * fmaxf(h1, 0.f);
        }
        float qs0 = sum2(q0), qs1 = sum2(q1);

        // block max
        float m = v1 ? fmaxf(g0, g1) : g0;
        #pragma unroll
        for (int o = 16; o; o >>= 1) m = fmaxf(m, __shfl_xor_sync(0xffffffffu, m, o));
        if (lane == 0) sredm[wid] = m;
        __syncthreads();
        float gmax = sredm[0];
        #pragma unroll
        for (int k = 1; k < NW; k++) gmax = fmaxf(gmax, sredm[k]);

        float w0 = __expf(g0 - gmax);
        float w1 = v1 ? __expf(g1 - gmax) : 0.f;

        // block sums of (w, w*q)
        float ssum = w0 + w1;
        float sq   = w0 * qs0 + w1 * qs1;
        #pragma unroll
        for (int o = 16; o; o >>= 1) {
            ssum += __shfl_xor_sync(0xffffffffu, ssum, o);
            sq   += __shfl_xor_sync(0xffffffffu, sq,   o);
        }
        if (lane == 0) { sreds[wid] = ssum; sredq[wid] = sq; }
        __syncthreads();

        if (t == 0) {
            float ts = 0.f, tq = 0.f;
            #pragma unroll
            for (int k = 0; k < NW; k++) { ts += sreds[k]; tq += sredq[k]; }
            float z = tq / ts + fcb;
            out[s] = 1.f / (1.f + __expf(-z));
        }
        parity ^= 1;
    }
}

extern "C" void kernel_launch(void* const* d_in, const int* in_sizes, int n_in,
                              void* d_out, int out_size) {
    const float* conts  = (const float*)d_in[0];
    const void*  cates  = d_in[1];
    const float* emb    = (const float*)d_in[3];
    const float* attn_W = (const float*)d_in[4];
    const float* attn_b = (const float*)d_in[5];
    const float* proj_W = (const float*)d_in[6];
    const float* fc_W   = (const float*)d_in[7];
    const float* fc_b   = (const float*)d_in[8];
    float* out = (float*)d_out;

    int batch = in_sizes[0] / CONTF;
    int nblk = batch < NBLK ? batch : NBLK;
    afm_main<<<nblk, TPB>>>(conts, cates, emb, attn_W, attn_b, proj_W,
                            fc_W, fc_b, out, batch);
}